// round 1
// baseline (speedup 1.0000x reference)
#include <cuda_runtime.h>
#include <math.h>

#define T_TOK   2048
#define DMODEL  1024
#define HQ      16
#define HD      64
#define BS      64
#define SSEL    16
#define NB      32
#define NEGV    (-1e30f)
#define SCALE   0.125f

// ---------------- device scratch (no runtime allocation allowed) ----------------
__device__ float g_q[T_TOK * HQ * HD];   // 8 MB
__device__ float g_k[T_TOK * HD];
__device__ float g_v[T_TOK * HD];
__device__ float g_g[T_TOK * 48];
__device__ float g_kc[NB * HD];
__device__ float g_vc[NB * HD];
__device__ float g_o[T_TOK * HQ * HD];   // 8 MB

// ---------------- generic SGEMM: C[M,N] = A[M,K] * B[N,K]^T ----------------
// BM=BN=128, BK=8, 256 threads, 8x8 per thread. M must be multiple of 128.
__global__ void __launch_bounds__(256, 2) sgemm_abt(
    const float* __restrict__ A, const float* __restrict__ B,
    float* __restrict__ C, int M, int N, int K)
{
    __shared__ float As[8][128];
    __shared__ float Bs[8][128];
    const int tid = threadIdx.x;
    const int tx = tid & 15, ty = tid >> 4;
    const int row0 = blockIdx.y * 128;
    const int col0 = blockIdx.x * 128;
    const int lr = tid >> 1;          // 0..127
    const int lc = (tid & 1) << 2;    // 0 or 4

    float acc[8][8] = {};
    const float* Ap = A + (size_t)(row0 + lr) * K + lc;
    const float* Bp = B + (size_t)(col0 + lr) * K + lc;
    const bool bok = (col0 + lr) < N;

    for (int k0 = 0; k0 < K; k0 += 8) {
        float4 a4 = *(const float4*)(Ap + k0);
        float4 b4 = bok ? *(const float4*)(Bp + k0) : make_float4(0.f, 0.f, 0.f, 0.f);
        __syncthreads();
        As[lc + 0][lr] = a4.x; As[lc + 1][lr] = a4.y;
        As[lc + 2][lr] = a4.z; As[lc + 3][lr] = a4.w;
        Bs[lc + 0][lr] = b4.x; Bs[lc + 1][lr] = b4.y;
        Bs[lc + 2][lr] = b4.z; Bs[lc + 3][lr] = b4.w;
        __syncthreads();
#pragma unroll
        for (int kk = 0; kk < 8; kk++) {
            float av[8], bv[8];
            *(float4*)&av[0] = *(const float4*)&As[kk][ty * 8];
            *(float4*)&av[4] = *(const float4*)&As[kk][ty * 8 + 4];
            *(float4*)&bv[0] = *(const float4*)&Bs[kk][tx * 8];
            *(float4*)&bv[4] = *(const float4*)&Bs[kk][tx * 8 + 4];
#pragma unroll
            for (int i = 0; i < 8; i++)
#pragma unroll
                for (int j = 0; j < 8; j++)
                    acc[i][j] += av[i] * bv[j];
        }
    }
#pragma unroll
    for (int i = 0; i < 8; i++) {
        int r = row0 + ty * 8 + i;
#pragma unroll
        for (int j = 0; j < 8; j++) {
            int c = col0 + tx * 8 + j;
            if (c < N) C[(size_t)r * N + c] = acc[i][j];
        }
    }
}

// ---------------- mean-pool K/V into block-compressed K_c, V_c ----------------
__global__ void pool_kv()
{
    int c = blockIdx.x;   // block id 0..31
    int d = threadIdx.x;  // dim 0..63
    float sk = 0.f, sv = 0.f;
    for (int s = 0; s < BS; s++) {
        sk += g_k[(c * BS + s) * HD + d];
        sv += g_v[(c * BS + s) * HD + d];
    }
    g_kc[c * HD + d] = sk * (1.f / BS);
    g_vc[c * HD + d] = sv * (1.f / BS);
}

// ---------------- fused per-token NSA: compressed attn + top-k + selected attn ----------------
__global__ void __launch_bounds__(256) nsa_attn()
{
    const int t    = blockIdx.x;
    const int tid  = threadIdx.x;
    const int lane = tid & 31;
    const int wid  = tid >> 5;

    __shared__ __align__(16) float qs[HQ * HD];     // 4 KB (persistent)
    __shared__ __align__(16) float ocmp[HQ * HD];   // 4 KB (persistent)
    __shared__ float pbuf[HQ * NB];                 // 2 KB (compressed scores/probs)
    __shared__ float impS[NB];
    __shared__ int   sel[SSEL];
    // union region: phase A = kc[32][65] + vc[32][65] (4160 f)
    //               phase B = kst[64][66] (4224) + vsm[64][64] (4096) + psm[16][64] (1024)
    __shared__ __align__(16) float un[9344];        // 36.5 KB

    const int cur  = t >> 6;
    const int nvis = (t + 1) >> 6;
    const float NINF = __int_as_float(0xff800000);

    // ---- load q row (1024 floats) ----
    {
        const float4* qsrc = (const float4*)(g_q + (size_t)t * HQ * HD);
        ((float4*)qs)[tid] = qsrc[tid];
    }
    // ---- load compressed K/V (padded to 65 to kill bank conflicts) ----
    for (int i = tid; i < NB * HD; i += 256) {
        int c = i >> 6, d = i & 63;
        un[c * 65 + d]        = g_kc[i];
        un[2080 + c * 65 + d] = g_vc[i];
    }
    __syncthreads();

    // ---- compressed scores (16 heads x 32 blocks) ----
    for (int i = tid; i < HQ * NB; i += 256) {
        int h = i >> 5, c = i & 31;
        const float* qh  = qs + h * HD;
        const float* kcc = un + c * 65;
        float s = 0.f;
#pragma unroll
        for (int d = 0; d < HD; d++) s += qh[d] * kcc[d];
        pbuf[i] = (c < nvis) ? s * SCALE : NEGV;
    }
    __syncthreads();

    // ---- softmax over visible blocks (warp w handles heads 2w, 2w+1) ----
    for (int hh = 0; hh < 2; hh++) {
        int h = wid * 2 + hh;
        float v = pbuf[h * NB + lane];
        float mx = v;
#pragma unroll
        for (int o = 16; o; o >>= 1) mx = fmaxf(mx, __shfl_xor_sync(0xffffffffu, mx, o));
        float e = (lane < nvis) ? __expf(v - mx) : 0.f;
        float sm = e;
#pragma unroll
        for (int o = 16; o; o >>= 1) sm += __shfl_xor_sync(0xffffffffu, sm, o);
        pbuf[h * NB + lane] = (sm > 0.f) ? e / sm : 0.f;
    }
    __syncthreads();

    // ---- o_cmp = p_cmp @ V_c ----
    {
        int h = tid >> 4, d0 = (tid & 15) << 2;
        float a0 = 0.f, a1 = 0.f, a2 = 0.f, a3 = 0.f;
#pragma unroll
        for (int c = 0; c < NB; c++) {
            float p = pbuf[h * NB + c];
            const float* vr = un + 2080 + c * 65 + d0;
            a0 += p * vr[0]; a1 += p * vr[1]; a2 += p * vr[2]; a3 += p * vr[3];
        }
        ocmp[h * HD + d0 + 0] = a0; ocmp[h * HD + d0 + 1] = a1;
        ocmp[h * HD + d0 + 2] = a2; ocmp[h * HD + d0 + 3] = a3;
    }
    // ---- block importance (sum over heads) + masks + forced blocks ----
    if (tid < NB) {
        int c = tid;
        float s = 0.f;
#pragma unroll
        for (int h = 0; h < HQ; h++) s += pbuf[h * NB + c];
        if (c > cur) s = NEGV;
        if (c == 0 || c == cur) s = __int_as_float(0x7f800000);  // +inf
        impS[c] = s;
    }
    __syncthreads();

    // ---- top-16 selection: serial argmax, strict > == lowest-index tie-break (matches lax.top_k)
    if (tid == 0) {
        for (int it = 0; it < SSEL; it++) {
            float best = NINF; int bi = 0;
            for (int c = 0; c < NB; c++) {
                float v = impS[c];
                if (v > best) { best = v; bi = c; }
            }
            sel[it] = bi;
            impS[bi] = NINF;
        }
    }
    __syncthreads();

    // ---- selected block-sparse attention, online softmax over 16 chunks ----
    float* kst = un;            // K^T [64 dims][66 pad] -> lane-conflict-free
    float* vsm = un + 4224;     // V   [64 keys][64 dims]
    float* psm = un + 8320;     // P   [16 heads][64 keys]

    const int h0 = wid * 2, h1 = h0 + 1;
    const int dk = lane * 2;                     // this lane owns keys/dims dk, dk+1
    float m0 = NEGV, m1 = NEGV, l0 = 0.f, l1 = 0.f;
    float2 acc0 = make_float2(0.f, 0.f), acc1 = make_float2(0.f, 0.f);

    for (int ib = 0; ib < SSEL; ib++) {
        int b = sel[ib];
        __syncthreads();  // protect smem reuse
        // load K (transposed) and V tiles: 4096 contiguous floats each
        const float4* kg = (const float4*)(g_k + (size_t)b * BS * HD);
        const float4* vg = (const float4*)(g_v + (size_t)b * BS * HD);
#pragma unroll
        for (int r = 0; r < 4; r++) {
            int f = tid + r * 256;
            float4 kq = kg[f];
            int e = f * 4, s = e >> 6, d = e & 63;
            kst[(d + 0) * 66 + s] = kq.x;
            kst[(d + 1) * 66 + s] = kq.y;
            kst[(d + 2) * 66 + s] = kq.z;
            kst[(d + 3) * 66 + s] = kq.w;
            ((float4*)vsm)[f] = vg[f];
        }
        __syncthreads();

        // scores for 2 keys x 2 heads
        float s00 = 0.f, s01 = 0.f, s10 = 0.f, s11 = 0.f;
#pragma unroll 8
        for (int d = 0; d < HD; d++) {
            float2 k2 = *(const float2*)&kst[d * 66 + dk];
            float q0 = qs[h0 * HD + d];
            float q1 = qs[h1 * HD + d];
            s00 += q0 * k2.x; s01 += q0 * k2.y;
            s10 += q1 * k2.x; s11 += q1 * k2.y;
        }
        int tokA = b * BS + dk;
        bool mA = (tokA <= t), mB = (tokA + 1 <= t);
        s00 = mA ? s00 * SCALE : NEGV;  s01 = mB ? s01 * SCALE : NEGV;
        s10 = mA ? s10 * SCALE : NEGV;  s11 = mB ? s11 * SCALE : NEGV;

        float c0 = fmaxf(s00, s01), c1 = fmaxf(s10, s11);
#pragma unroll
        for (int o = 16; o; o >>= 1) {
            c0 = fmaxf(c0, __shfl_xor_sync(0xffffffffu, c0, o));
            c1 = fmaxf(c1, __shfl_xor_sync(0xffffffffu, c1, o));
        }
        float mn0 = fmaxf(m0, c0), mn1 = fmaxf(m1, c1);
        float al0 = __expf(m0 - mn0), al1 = __expf(m1 - mn1);
        float p00 = __expf(s00 - mn0), p01 = __expf(s01 - mn0);
        float p10 = __expf(s10 - mn1), p11 = __expf(s11 - mn1);
        float ls0 = p00 + p01, ls1 = p10 + p11;
#pragma unroll
        for (int o = 16; o; o >>= 1) {
            ls0 += __shfl_xor_sync(0xffffffffu, ls0, o);
            ls1 += __shfl_xor_sync(0xffffffffu, ls1, o);
        }
        l0 = l0 * al0 + ls0;  l1 = l1 * al1 + ls1;
        m0 = mn0;  m1 = mn1;

        psm[h0 * HD + dk] = p00;  psm[h0 * HD + dk + 1] = p01;
        psm[h1 * HD + dk] = p10;  psm[h1 * HD + dk + 1] = p11;
        __syncwarp();

        acc0.x *= al0; acc0.y *= al0; acc1.x *= al1; acc1.y *= al1;
#pragma unroll 8
        for (int s = 0; s < BS; s++) {
            float2 v2 = *(const float2*)&vsm[s * HD + dk];
            float p0 = psm[h0 * HD + s];
            float p1 = psm[h1 * HD + s];
            acc0.x += p0 * v2.x; acc0.y += p0 * v2.y;
            acc1.x += p1 * v2.x; acc1.y += p1 * v2.y;
        }
    }

    // ---- gate + combine, write combined o ----
    const float* pg = g_g + (size_t)t * 48;
    float gc0 = 1.f / (1.f + __expf(-pg[h0 * 3 + 0]));
    float gs0 = 1.f / (1.f + __expf(-pg[h0 * 3 + 1]));
    float gc1 = 1.f / (1.f + __expf(-pg[h1 * 3 + 0]));
    float gs1 = 1.f / (1.f + __expf(-pg[h1 * 3 + 1]));
    float inv0 = 1.f / l0, inv1 = 1.f / l1;
    float* od = g_o + (size_t)t * HQ * HD;
    od[h0 * HD + dk]     = acc0.x * inv0 * gs0 + ocmp[h0 * HD + dk]     * gc0;
    od[h0 * HD + dk + 1] = acc0.y * inv0 * gs0 + ocmp[h0 * HD + dk + 1] * gc0;
    od[h1 * HD + dk]     = acc1.x * inv1 * gs1 + ocmp[h1 * HD + dk]     * gc1;
    od[h1 * HD + dk + 1] = acc1.y * inv1 * gs1 + ocmp[h1 * HD + dk + 1] * gc1;
}

// ---------------- launch ----------------
extern "C" void kernel_launch(void* const* d_in, const int* in_sizes, int n_in,
                              void* d_out, int out_size)
{
    (void)in_sizes; (void)n_in; (void)out_size;
    const float* x  = (const float*)d_in[0];
    const float* Wq = (const float*)d_in[1];
    const float* Wk = (const float*)d_in[2];
    const float* Wv = (const float*)d_in[3];
    const float* Wg = (const float*)d_in[4];
    const float* Wo = (const float*)d_in[5];
    float* out = (float*)d_out;

    float *q, *k, *v, *g, *o;
    cudaGetSymbolAddress((void**)&q, g_q);
    cudaGetSymbolAddress((void**)&k, g_k);
    cudaGetSymbolAddress((void**)&v, g_v);
    cudaGetSymbolAddress((void**)&g, g_g);
    cudaGetSymbolAddress((void**)&o, g_o);

    dim3 blk(256);
    dim3 grid_big((DMODEL + 127) / 128, T_TOK / 128);   // 8 x 16
    dim3 grid_sml(1, T_TOK / 128);                      // 1 x 16

    sgemm_abt<<<grid_big, blk>>>(x, Wq, q, T_TOK, HQ * HD, DMODEL);
    sgemm_abt<<<grid_sml, blk>>>(x, Wk, k, T_TOK, HD, DMODEL);
    sgemm_abt<<<grid_sml, blk>>>(x, Wv, v, T_TOK, HD, DMODEL);
    sgemm_abt<<<grid_sml, blk>>>(x, Wg, g, T_TOK, 48, DMODEL);
    pool_kv<<<NB, HD>>>();
    nsa_attn<<<T_TOK, 256>>>();
    sgemm_abt<<<grid_big, blk>>>(o, Wo, out, T_TOK, DMODEL, DMODEL);
}

// round 2
// speedup vs baseline: 1.4041x; 1.4041x over previous
#include <cuda_runtime.h>
#include <math.h>

#define T_TOK   2048
#define DMODEL  1024
#define HQ      16
#define HD      64
#define BS      64
#define SSEL    16
#define NB      32
#define NEGV    (-1e30f)
#define SCALE   0.125f

// ---------------- device scratch (no runtime allocation allowed) ----------------
__device__ float g_q[T_TOK * HQ * HD];   // 8 MB
__device__ float g_k[T_TOK * HD];
__device__ float g_v[T_TOK * HD];
__device__ float g_g[T_TOK * 48];
__device__ float g_kc[NB * HD];
__device__ float g_vc[NB * HD];
__device__ float g_o[T_TOK * HQ * HD];   // 8 MB

// ---------------- big SGEMM: C[M,N] = A[M,K] * B[N,K]^T ----------------
// BM=BN=128, BK=8, 256 threads, 8x8 per thread, double-buffered smem.
__global__ void __launch_bounds__(256, 2) sgemm_abt(
    const float* __restrict__ A, const float* __restrict__ B,
    float* __restrict__ C, int M, int N, int K)
{
    __shared__ float As[2][8][128];
    __shared__ float Bs[2][8][128];
    const int tid = threadIdx.x;
    const int tx = tid & 15, ty = tid >> 4;
    const int row0 = blockIdx.y * 128;
    const int col0 = blockIdx.x * 128;
    const int lr = tid >> 1;          // 0..127
    const int lc = (tid & 1) << 2;    // 0 or 4

    float acc[8][8] = {};
    const float* Ap = A + (size_t)(row0 + lr) * K + lc;
    const float* Bp = B + (size_t)(col0 + lr) * K + lc;
    const bool bok = (col0 + lr) < N;
    const int ntiles = K >> 3;

    // prologue: tile 0
    {
        float4 a4 = *(const float4*)(Ap);
        float4 b4 = bok ? *(const float4*)(Bp) : make_float4(0.f, 0.f, 0.f, 0.f);
        As[0][lc + 0][lr] = a4.x; As[0][lc + 1][lr] = a4.y;
        As[0][lc + 2][lr] = a4.z; As[0][lc + 3][lr] = a4.w;
        Bs[0][lc + 0][lr] = b4.x; Bs[0][lc + 1][lr] = b4.y;
        Bs[0][lc + 2][lr] = b4.z; Bs[0][lc + 3][lr] = b4.w;
    }
    __syncthreads();

    int buf = 0;
    for (int tI = 0; tI < ntiles; tI++) {
        float4 na, nb_;
        const bool more = (tI + 1) < ntiles;
        if (more) {
            int k0 = (tI + 1) << 3;
            na  = *(const float4*)(Ap + k0);
            nb_ = bok ? *(const float4*)(Bp + k0) : make_float4(0.f, 0.f, 0.f, 0.f);
        }
#pragma unroll
        for (int kk = 0; kk < 8; kk++) {
            float av[8], bv[8];
            *(float4*)&av[0] = *(const float4*)&As[buf][kk][ty * 8];
            *(float4*)&av[4] = *(const float4*)&As[buf][kk][ty * 8 + 4];
            *(float4*)&bv[0] = *(const float4*)&Bs[buf][kk][tx * 8];
            *(float4*)&bv[4] = *(const float4*)&Bs[buf][kk][tx * 8 + 4];
#pragma unroll
            for (int i = 0; i < 8; i++)
#pragma unroll
                for (int j = 0; j < 8; j++)
                    acc[i][j] += av[i] * bv[j];
        }
        if (more) {
            int nbuf = buf ^ 1;
            As[nbuf][lc + 0][lr] = na.x;  As[nbuf][lc + 1][lr] = na.y;
            As[nbuf][lc + 2][lr] = na.z;  As[nbuf][lc + 3][lr] = na.w;
            Bs[nbuf][lc + 0][lr] = nb_.x; Bs[nbuf][lc + 1][lr] = nb_.y;
            Bs[nbuf][lc + 2][lr] = nb_.z; Bs[nbuf][lc + 3][lr] = nb_.w;
            __syncthreads();
            buf = nbuf;
        }
    }
#pragma unroll
    for (int i = 0; i < 8; i++) {
        int r = row0 + ty * 8 + i;
#pragma unroll
        for (int j = 0; j < 8; j++) {
            int c = col0 + tx * 8 + j;
            if (c < N) C[(size_t)r * N + c] = acc[i][j];
        }
    }
}

// ---------------- fused skinny projections: K (N=64), V (N=64), G (N=48) ----------------
// grid = (3 mats, 32 M-tiles), BM=64, BN=64, BK=16, 256 threads, 4x4/thread, double-buffered
__global__ void __launch_bounds__(256, 2) proj_small(
    const float* __restrict__ x,
    const float* __restrict__ Wk, const float* __restrict__ Wv, const float* __restrict__ Wg)
{
    const int mat  = blockIdx.x;
    const int row0 = blockIdx.y * 64;
    const float* Bw = (mat == 0) ? Wk : (mat == 1) ? Wv : Wg;
    float* C        = (mat == 0) ? g_k : (mat == 1) ? g_v : g_g;
    const int N     = (mat == 2) ? 48 : 64;

    __shared__ float As[2][16][64];
    __shared__ float Bs[2][16][64];
    const int tid = threadIdx.x;
    const int tx = tid & 15, ty = tid >> 4;
    const int lr = tid >> 2;          // 0..63
    const int lk = (tid & 3) << 2;    // 0,4,8,12

    const float* Ap = x  + (size_t)(row0 + lr) * DMODEL + lk;
    const float* Bp = Bw + (size_t)lr * DMODEL + lk;
    const bool bok = lr < N;

    float acc[4][4] = {};

    {
        float4 a4 = *(const float4*)(Ap);
        float4 b4 = bok ? *(const float4*)(Bp) : make_float4(0.f, 0.f, 0.f, 0.f);
        As[0][lk + 0][lr] = a4.x; As[0][lk + 1][lr] = a4.y;
        As[0][lk + 2][lr] = a4.z; As[0][lk + 3][lr] = a4.w;
        Bs[0][lk + 0][lr] = b4.x; Bs[0][lk + 1][lr] = b4.y;
        Bs[0][lk + 2][lr] = b4.z; Bs[0][lk + 3][lr] = b4.w;
    }
    __syncthreads();

    const int ntiles = DMODEL / 16;   // 64
    int buf = 0;
    for (int tI = 0; tI < ntiles; tI++) {
        float4 na, nb_;
        const bool more = (tI + 1) < ntiles;
        if (more) {
            int k0 = (tI + 1) * 16;
            na  = *(const float4*)(Ap + k0);
            nb_ = bok ? *(const float4*)(Bp + k0) : make_float4(0.f, 0.f, 0.f, 0.f);
        }
#pragma unroll
        for (int kk = 0; kk < 16; kk++) {
            float av[4], bv[4];
            *(float4*)&av[0] = *(const float4*)&As[buf][kk][ty * 4];
            *(float4*)&bv[0] = *(const float4*)&Bs[buf][kk][tx * 4];
#pragma unroll
            for (int i = 0; i < 4; i++)
#pragma unroll
                for (int j = 0; j < 4; j++)
                    acc[i][j] += av[i] * bv[j];
        }
        if (more) {
            int nbuf = buf ^ 1;
            As[nbuf][lk + 0][lr] = na.x;  As[nbuf][lk + 1][lr] = na.y;
            As[nbuf][lk + 2][lr] = na.z;  As[nbuf][lk + 3][lr] = na.w;
            Bs[nbuf][lk + 0][lr] = nb_.x; Bs[nbuf][lk + 1][lr] = nb_.y;
            Bs[nbuf][lk + 2][lr] = nb_.z; Bs[nbuf][lk + 3][lr] = nb_.w;
            __syncthreads();
            buf = nbuf;
        }
    }
#pragma unroll
    for (int i = 0; i < 4; i++) {
        int r = row0 + ty * 4 + i;
#pragma unroll
        for (int j = 0; j < 4; j++) {
            int c = tx * 4 + j;
            if (c < N) C[(size_t)r * N + c] = acc[i][j];
        }
    }
}

// ---------------- mean-pool K/V into block-compressed K_c, V_c ----------------
__global__ void pool_kv()
{
    int c = blockIdx.x;
    int d = threadIdx.x;
    float sk = 0.f, sv = 0.f;
    for (int s = 0; s < BS; s++) {
        sk += g_k[(c * BS + s) * HD + d];
        sv += g_v[(c * BS + s) * HD + d];
    }
    g_kc[c * HD + d] = sk * (1.f / BS);
    g_vc[c * HD + d] = sv * (1.f / BS);
}

// ---------------- fused per-token NSA: compressed attn + top-k + selected attn ----------------
__global__ void __launch_bounds__(256) nsa_attn()
{
    const int t    = blockIdx.x;
    const int tid  = threadIdx.x;
    const int lane = tid & 31;
    const int wid  = tid >> 5;

    __shared__ __align__(16) float qs[HQ * HD];
    __shared__ __align__(16) float ocmp[HQ * HD];
    __shared__ float pbuf[HQ * NB];
    __shared__ float impS[NB];
    __shared__ int   sel[SSEL];
    __shared__ __align__(16) float un[9344];

    const int cur  = t >> 6;
    const int nvis = (t + 1) >> 6;
    const float NINF = __int_as_float(0xff800000);

    {
        const float4* qsrc = (const float4*)(g_q + (size_t)t * HQ * HD);
        ((float4*)qs)[tid] = qsrc[tid];
    }
    for (int i = tid; i < NB * HD; i += 256) {
        int c = i >> 6, d = i & 63;
        un[c * 65 + d]        = g_kc[i];
        un[2080 + c * 65 + d] = g_vc[i];
    }
    __syncthreads();

    for (int i = tid; i < HQ * NB; i += 256) {
        int h = i >> 5, c = i & 31;
        const float* qh  = qs + h * HD;
        const float* kcc = un + c * 65;
        float s = 0.f;
#pragma unroll
        for (int d = 0; d < HD; d++) s += qh[d] * kcc[d];
        pbuf[i] = (c < nvis) ? s * SCALE : NEGV;
    }
    __syncthreads();

    for (int hh = 0; hh < 2; hh++) {
        int h = wid * 2 + hh;
        float v = pbuf[h * NB + lane];
        float mx = v;
#pragma unroll
        for (int o = 16; o; o >>= 1) mx = fmaxf(mx, __shfl_xor_sync(0xffffffffu, mx, o));
        float e = (lane < nvis) ? __expf(v - mx) : 0.f;
        float sm = e;
#pragma unroll
        for (int o = 16; o; o >>= 1) sm += __shfl_xor_sync(0xffffffffu, sm, o);
        pbuf[h * NB + lane] = (sm > 0.f) ? e / sm : 0.f;
    }
    __syncthreads();

    {
        int h = tid >> 4, d0 = (tid & 15) << 2;
        float a0 = 0.f, a1 = 0.f, a2 = 0.f, a3 = 0.f;
#pragma unroll
        for (int c = 0; c < NB; c++) {
            float p = pbuf[h * NB + c];
            const float* vr = un + 2080 + c * 65 + d0;
            a0 += p * vr[0]; a1 += p * vr[1]; a2 += p * vr[2]; a3 += p * vr[3];
        }
        ocmp[h * HD + d0 + 0] = a0; ocmp[h * HD + d0 + 1] = a1;
        ocmp[h * HD + d0 + 2] = a2; ocmp[h * HD + d0 + 3] = a3;
    }
    if (tid < NB) {
        int c = tid;
        float s = 0.f;
#pragma unroll
        for (int h = 0; h < HQ; h++) s += pbuf[h * NB + c];
        if (c > cur) s = NEGV;
        if (c == 0 || c == cur) s = __int_as_float(0x7f800000);
        impS[c] = s;
    }
    __syncthreads();

    if (tid == 0) {
        for (int it = 0; it < SSEL; it++) {
            float best = NINF; int bi = 0;
            for (int c = 0; c < NB; c++) {
                float v = impS[c];
                if (v > best) { best = v; bi = c; }
            }
            sel[it] = bi;
            impS[bi] = NINF;
        }
    }
    __syncthreads();

    float* kst = un;
    float* vsm = un + 4224;
    float* psm = un + 8320;

    const int h0 = wid * 2, h1 = h0 + 1;
    const int dk = lane * 2;
    float m0 = NEGV, m1 = NEGV, l0 = 0.f, l1 = 0.f;
    float2 acc0 = make_float2(0.f, 0.f), acc1 = make_float2(0.f, 0.f);

    for (int ib = 0; ib < SSEL; ib++) {
        int b = sel[ib];
        __syncthreads();
        const float4* kg = (const float4*)(g_k + (size_t)b * BS * HD);
        const float4* vg = (const float4*)(g_v + (size_t)b * BS * HD);
#pragma unroll
        for (int r = 0; r < 4; r++) {
            int f = tid + r * 256;
            float4 kq = kg[f];
            int e = f * 4, s = e >> 6, d = e & 63;
            kst[(d + 0) * 66 + s] = kq.x;
            kst[(d + 1) * 66 + s] = kq.y;
            kst[(d + 2) * 66 + s] = kq.z;
            kst[(d + 3) * 66 + s] = kq.w;
            ((float4*)vsm)[f] = vg[f];
        }
        __syncthreads();

        float s00 = 0.f, s01 = 0.f, s10 = 0.f, s11 = 0.f;
#pragma unroll 8
        for (int d = 0; d < HD; d++) {
            float2 k2 = *(const float2*)&kst[d * 66 + dk];
            float q0 = qs[h0 * HD + d];
            float q1 = qs[h1 * HD + d];
            s00 += q0 * k2.x; s01 += q0 * k2.y;
            s10 += q1 * k2.x; s11 += q1 * k2.y;
        }
        int tokA = b * BS + dk;
        bool mA = (tokA <= t), mB = (tokA + 1 <= t);
        s00 = mA ? s00 * SCALE : NEGV;  s01 = mB ? s01 * SCALE : NEGV;
        s10 = mA ? s10 * SCALE : NEGV;  s11 = mB ? s11 * SCALE : NEGV;

        float c0 = fmaxf(s00, s01), c1 = fmaxf(s10, s11);
#pragma unroll
        for (int o = 16; o; o >>= 1) {
            c0 = fmaxf(c0, __shfl_xor_sync(0xffffffffu, c0, o));
            c1 = fmaxf(c1, __shfl_xor_sync(0xffffffffu, c1, o));
        }
        float mn0 = fmaxf(m0, c0), mn1 = fmaxf(m1, c1);
        float al0 = __expf(m0 - mn0), al1 = __expf(m1 - mn1);
        float p00 = __expf(s00 - mn0), p01 = __expf(s01 - mn0);
        float p10 = __expf(s10 - mn1), p11 = __expf(s11 - mn1);
        float ls0 = p00 + p01, ls1 = p10 + p11;
#pragma unroll
        for (int o = 16; o; o >>= 1) {
            ls0 += __shfl_xor_sync(0xffffffffu, ls0, o);
            ls1 += __shfl_xor_sync(0xffffffffu, ls1, o);
        }
        l0 = l0 * al0 + ls0;  l1 = l1 * al1 + ls1;
        m0 = mn0;  m1 = mn1;

        psm[h0 * HD + dk] = p00;  psm[h0 * HD + dk + 1] = p01;
        psm[h1 * HD + dk] = p10;  psm[h1 * HD + dk + 1] = p11;
        __syncwarp();

        acc0.x *= al0; acc0.y *= al0; acc1.x *= al1; acc1.y *= al1;
#pragma unroll 8
        for (int s = 0; s < BS; s++) {
            float2 v2 = *(const float2*)&vsm[s * HD + dk];
            float p0 = psm[h0 * HD + s];
            float p1 = psm[h1 * HD + s];
            acc0.x += p0 * v2.x; acc0.y += p0 * v2.y;
            acc1.x += p1 * v2.x; acc1.y += p1 * v2.y;
        }
    }

    const float* pg = g_g + (size_t)t * 48;
    float gc0 = 1.f / (1.f + __expf(-pg[h0 * 3 + 0]));
    float gs0 = 1.f / (1.f + __expf(-pg[h0 * 3 + 1]));
    float gc1 = 1.f / (1.f + __expf(-pg[h1 * 3 + 0]));
    float gs1 = 1.f / (1.f + __expf(-pg[h1 * 3 + 1]));
    float inv0 = 1.f / l0, inv1 = 1.f / l1;
    float* od = g_o + (size_t)t * HQ * HD;
    od[h0 * HD + dk]     = acc0.x * inv0 * gs0 + ocmp[h0 * HD + dk]     * gc0;
    od[h0 * HD + dk + 1] = acc0.y * inv0 * gs0 + ocmp[h0 * HD + dk + 1] * gc0;
    od[h1 * HD + dk]     = acc1.x * inv1 * gs1 + ocmp[h1 * HD + dk]     * gc1;
    od[h1 * HD + dk + 1] = acc1.y * inv1 * gs1 + ocmp[h1 * HD + dk + 1] * gc1;
}

// ---------------- launch ----------------
extern "C" void kernel_launch(void* const* d_in, const int* in_sizes, int n_in,
                              void* d_out, int out_size)
{
    (void)in_sizes; (void)n_in; (void)out_size;
    const float* x  = (const float*)d_in[0];
    const float* Wq = (const float*)d_in[1];
    const float* Wk = (const float*)d_in[2];
    const float* Wv = (const float*)d_in[3];
    const float* Wg = (const float*)d_in[4];
    const float* Wo = (const float*)d_in[5];
    float* out = (float*)d_out;

    float *q, *o;
    cudaGetSymbolAddress((void**)&q, g_q);
    cudaGetSymbolAddress((void**)&o, g_o);

    dim3 blk(256);
    dim3 grid_big((DMODEL + 127) / 128, T_TOK / 128);   // 8 x 16

    sgemm_abt<<<grid_big, blk>>>(x, Wq, q, T_TOK, HQ * HD, DMODEL);
    proj_small<<<dim3(3, T_TOK / 64), blk>>>(x, Wk, Wv, Wg);
    pool_kv<<<NB, HD>>>();
    nsa_attn<<<T_TOK, 256>>>();
    sgemm_abt<<<grid_big, blk>>>(o, Wo, out, T_TOK, DMODEL, DMODEL);
}

// round 3
// speedup vs baseline: 1.4760x; 1.0512x over previous
#include <cuda_runtime.h>
#include <math.h>

#define T_TOK   2048
#define DMODEL  1024
#define HQ      16
#define HD      64
#define BS      64
#define SSEL    16
#define NB      32
#define NEGV    (-1e30f)
#define SCALE   0.125f

// XOR swizzle for the K^T tile: keeps both transposed STS and float2 LDS conflict-free
#define SWZ(d) ((((d) >> 2) & 15) << 1)

// ---------------- device scratch ----------------
__device__ float g_q[T_TOK * HQ * HD];
__device__ float g_k[T_TOK * HD];
__device__ float g_v[T_TOK * HD];
__device__ float g_g[T_TOK * 48];
__device__ float g_kc[NB * HD];
__device__ float g_vc[NB * HD];
__device__ float g_o[T_TOK * HQ * HD];

// ---------------- big SGEMM: C[M,N] = A[M,K] * B[N,K]^T ----------------
__global__ void __launch_bounds__(256, 2) sgemm_abt(
    const float* __restrict__ A, const float* __restrict__ B,
    float* __restrict__ C, int M, int N, int K)
{
    __shared__ float As[2][8][128];
    __shared__ float Bs[2][8][128];
    const int tid = threadIdx.x;
    const int tx = tid & 15, ty = tid >> 4;
    const int row0 = blockIdx.y * 128;
    const int col0 = blockIdx.x * 128;
    const int lr = tid >> 1;
    const int lc = (tid & 1) << 2;

    float acc[8][8] = {};
    const float* Ap = A + (size_t)(row0 + lr) * K + lc;
    const float* Bp = B + (size_t)(col0 + lr) * K + lc;
    const bool bok = (col0 + lr) < N;
    const int ntiles = K >> 3;

    {
        float4 a4 = *(const float4*)(Ap);
        float4 b4 = bok ? *(const float4*)(Bp) : make_float4(0.f, 0.f, 0.f, 0.f);
        As[0][lc + 0][lr] = a4.x; As[0][lc + 1][lr] = a4.y;
        As[0][lc + 2][lr] = a4.z; As[0][lc + 3][lr] = a4.w;
        Bs[0][lc + 0][lr] = b4.x; Bs[0][lc + 1][lr] = b4.y;
        Bs[0][lc + 2][lr] = b4.z; Bs[0][lc + 3][lr] = b4.w;
    }
    __syncthreads();

    int buf = 0;
    for (int tI = 0; tI < ntiles; tI++) {
        float4 na, nb_;
        const bool more = (tI + 1) < ntiles;
        if (more) {
            int k0 = (tI + 1) << 3;
            na  = *(const float4*)(Ap + k0);
            nb_ = bok ? *(const float4*)(Bp + k0) : make_float4(0.f, 0.f, 0.f, 0.f);
        }
#pragma unroll
        for (int kk = 0; kk < 8; kk++) {
            float av[8], bv[8];
            *(float4*)&av[0] = *(const float4*)&As[buf][kk][ty * 8];
            *(float4*)&av[4] = *(const float4*)&As[buf][kk][ty * 8 + 4];
            *(float4*)&bv[0] = *(const float4*)&Bs[buf][kk][tx * 8];
            *(float4*)&bv[4] = *(const float4*)&Bs[buf][kk][tx * 8 + 4];
#pragma unroll
            for (int i = 0; i < 8; i++)
#pragma unroll
                for (int j = 0; j < 8; j++)
                    acc[i][j] += av[i] * bv[j];
        }
        if (more) {
            int nbuf = buf ^ 1;
            As[nbuf][lc + 0][lr] = na.x;  As[nbuf][lc + 1][lr] = na.y;
            As[nbuf][lc + 2][lr] = na.z;  As[nbuf][lc + 3][lr] = na.w;
            Bs[nbuf][lc + 0][lr] = nb_.x; Bs[nbuf][lc + 1][lr] = nb_.y;
            Bs[nbuf][lc + 2][lr] = nb_.z; Bs[nbuf][lc + 3][lr] = nb_.w;
            __syncthreads();
            buf = nbuf;
        }
    }
#pragma unroll
    for (int i = 0; i < 8; i++) {
        int r = row0 + ty * 8 + i;
#pragma unroll
        for (int j = 0; j < 8; j++) {
            int c = col0 + tx * 8 + j;
            if (c < N) C[(size_t)r * N + c] = acc[i][j];
        }
    }
}

// ---------------- fused skinny projections: K, V, G ----------------
__global__ void __launch_bounds__(256, 2) proj_small(
    const float* __restrict__ x,
    const float* __restrict__ Wk, const float* __restrict__ Wv, const float* __restrict__ Wg)
{
    const int mat  = blockIdx.x;
    const int row0 = blockIdx.y * 64;
    const float* Bw = (mat == 0) ? Wk : (mat == 1) ? Wv : Wg;
    float* C        = (mat == 0) ? g_k : (mat == 1) ? g_v : g_g;
    const int N     = (mat == 2) ? 48 : 64;

    __shared__ float As[2][16][64];
    __shared__ float Bs[2][16][64];
    const int tid = threadIdx.x;
    const int tx = tid & 15, ty = tid >> 4;
    const int lr = tid >> 2;
    const int lk = (tid & 3) << 2;

    const float* Ap = x  + (size_t)(row0 + lr) * DMODEL + lk;
    const float* Bp = Bw + (size_t)lr * DMODEL + lk;
    const bool bok = lr < N;

    float acc[4][4] = {};
    {
        float4 a4 = *(const float4*)(Ap);
        float4 b4 = bok ? *(const float4*)(Bp) : make_float4(0.f, 0.f, 0.f, 0.f);
        As[0][lk + 0][lr] = a4.x; As[0][lk + 1][lr] = a4.y;
        As[0][lk + 2][lr] = a4.z; As[0][lk + 3][lr] = a4.w;
        Bs[0][lk + 0][lr] = b4.x; Bs[0][lk + 1][lr] = b4.y;
        Bs[0][lk + 2][lr] = b4.z; Bs[0][lk + 3][lr] = b4.w;
    }
    __syncthreads();

    const int ntiles = DMODEL / 16;
    int buf = 0;
    for (int tI = 0; tI < ntiles; tI++) {
        float4 na, nb_;
        const bool more = (tI + 1) < ntiles;
        if (more) {
            int k0 = (tI + 1) * 16;
            na  = *(const float4*)(Ap + k0);
            nb_ = bok ? *(const float4*)(Bp + k0) : make_float4(0.f, 0.f, 0.f, 0.f);
        }
#pragma unroll
        for (int kk = 0; kk < 16; kk++) {
            float av[4], bv[4];
            *(float4*)&av[0] = *(const float4*)&As[buf][kk][ty * 4];
            *(float4*)&bv[0] = *(const float4*)&Bs[buf][kk][tx * 4];
#pragma unroll
            for (int i = 0; i < 4; i++)
#pragma unroll
                for (int j = 0; j < 4; j++)
                    acc[i][j] += av[i] * bv[j];
        }
        if (more) {
            int nbuf = buf ^ 1;
            As[nbuf][lk + 0][lr] = na.x;  As[nbuf][lk + 1][lr] = na.y;
            As[nbuf][lk + 2][lr] = na.z;  As[nbuf][lk + 3][lr] = na.w;
            Bs[nbuf][lk + 0][lr] = nb_.x; Bs[nbuf][lk + 1][lr] = nb_.y;
            Bs[nbuf][lk + 2][lr] = nb_.z; Bs[nbuf][lk + 3][lr] = nb_.w;
            __syncthreads();
            buf = nbuf;
        }
    }
#pragma unroll
    for (int i = 0; i < 4; i++) {
        int r = row0 + ty * 4 + i;
#pragma unroll
        for (int j = 0; j < 4; j++) {
            int c = tx * 4 + j;
            if (c < N) C[(size_t)r * N + c] = acc[i][j];
        }
    }
}

// ---------------- mean-pool K/V ----------------
__global__ void pool_kv()
{
    int c = blockIdx.x;
    int d = threadIdx.x;
    float sk = 0.f, sv = 0.f;
    for (int s = 0; s < BS; s++) {
        sk += g_k[(c * BS + s) * HD + d];
        sv += g_v[(c * BS + s) * HD + d];
    }
    g_kc[c * HD + d] = sk * (1.f / BS);
    g_vc[c * HD + d] = sv * (1.f / BS);
}

// ---------------- fused per-token NSA ----------------
__global__ void __launch_bounds__(256) nsa_attn()
{
    const int t    = blockIdx.x;
    const int tid  = threadIdx.x;
    const int lane = tid & 31;
    const int wid  = tid >> 5;

    __shared__ __align__(16) float qs[HQ * HD];
    __shared__ __align__(16) float ocmp[HQ * HD];
    __shared__ float pbuf[HQ * NB];
    __shared__ float impS[NB];
    __shared__ int   sel[SSEL];
    __shared__ __align__(16) float un[9344];

    const int cur  = t >> 6;
    const int nvis = (t + 1) >> 6;
    const float NINF = __int_as_float(0xff800000);

    {
        const float4* qsrc = (const float4*)(g_q + (size_t)t * HQ * HD);
        ((float4*)qs)[tid] = qsrc[tid];
    }
    for (int i = tid; i < NB * HD; i += 256) {
        int c = i >> 6, d = i & 63;
        un[c * 65 + d]        = g_kc[i];
        un[2080 + c * 65 + d] = g_vc[i];
    }
    __syncthreads();

    for (int i = tid; i < HQ * NB; i += 256) {
        int h = i >> 5, c = i & 31;
        const float* qh  = qs + h * HD;
        const float* kcc = un + c * 65;
        float s = 0.f;
#pragma unroll
        for (int d = 0; d < HD; d++) s += qh[d] * kcc[d];
        pbuf[i] = (c < nvis) ? s * SCALE : NEGV;
    }
    __syncthreads();

    for (int hh = 0; hh < 2; hh++) {
        int h = wid * 2 + hh;
        float v = pbuf[h * NB + lane];
        float mx = v;
#pragma unroll
        for (int o = 16; o; o >>= 1) mx = fmaxf(mx, __shfl_xor_sync(0xffffffffu, mx, o));
        float e = (lane < nvis) ? __expf(v - mx) : 0.f;
        float sm = e;
#pragma unroll
        for (int o = 16; o; o >>= 1) sm += __shfl_xor_sync(0xffffffffu, sm, o);
        pbuf[h * NB + lane] = (sm > 0.f) ? e / sm : 0.f;
    }
    __syncthreads();

    {
        int h = tid >> 4, d0 = (tid & 15) << 2;
        float a0 = 0.f, a1 = 0.f, a2 = 0.f, a3 = 0.f;
#pragma unroll
        for (int c = 0; c < NB; c++) {
            float p = pbuf[h * NB + c];
            const float* vr = un + 2080 + c * 65 + d0;
            a0 += p * vr[0]; a1 += p * vr[1]; a2 += p * vr[2]; a3 += p * vr[3];
        }
        ocmp[h * HD + d0 + 0] = a0; ocmp[h * HD + d0 + 1] = a1;
        ocmp[h * HD + d0 + 2] = a2; ocmp[h * HD + d0 + 3] = a3;
    }
    if (tid < NB) {
        int c = tid;
        float s = 0.f;
#pragma unroll
        for (int h = 0; h < HQ; h++) s += pbuf[h * NB + c];
        if (c > cur) s = NEGV;
        if (c == 0 || c == cur) s = __int_as_float(0x7f800000);
        impS[c] = s;
    }
    __syncthreads();

    if (tid == 0) {
        for (int it = 0; it < SSEL; it++) {
            float best = NINF; int bi = 0;
            for (int c = 0; c < NB; c++) {
                float v = impS[c];
                if (v > best) { best = v; bi = c; }
            }
            sel[it] = bi;
            impS[bi] = NINF;
        }
    }
    __syncthreads();

    float* kst = un;            // K^T [64 dims][66], XOR-swizzled in s
    float* vsm = un + 4224;     // V   [64 keys][64 dims]
    float* psm = un + 8320;     // P   [16 heads][64 keys]

    const int h0 = wid * 2, h1 = h0 + 1;
    const int dk = lane * 2;
    float m0 = NEGV, m1 = NEGV, l0 = 0.f, l1 = 0.f;
    float2 acc0 = make_float2(0.f, 0.f), acc1 = make_float2(0.f, 0.f);

    for (int ib = 0; ib < SSEL; ib++) {
        int b = sel[ib];
        __syncthreads();
        const float4* kg = (const float4*)(g_k + (size_t)b * BS * HD);
        const float4* vg = (const float4*)(g_v + (size_t)b * BS * HD);
#pragma unroll
        for (int r = 0; r < 4; r++) {
            int f = tid + r * 256;
            float4 kq = kg[f];
            int e = f * 4, s = e >> 6, d = e & 63;
            int sw = s ^ SWZ(d);        // SWZ constant over d..d+3
            kst[(d + 0) * 66 + sw] = kq.x;
            kst[(d + 1) * 66 + sw] = kq.y;
            kst[(d + 2) * 66 + sw] = kq.z;
            kst[(d + 3) * 66 + sw] = kq.w;
            ((float4*)vsm)[f] = vg[f];
        }
        __syncthreads();

        // ---- scores: 2 heads x 2 keys, d in quads, float4 q-broadcasts ----
        float s00 = 0.f, s01 = 0.f, s10 = 0.f, s11 = 0.f;
#pragma unroll
        for (int d = 0; d < HD; d += 4) {
            float4 q0 = *(const float4*)&qs[h0 * HD + d];
            float4 q1 = *(const float4*)&qs[h1 * HD + d];
            int sk = dk ^ SWZ(d);
            float2 k0 = *(const float2*)&kst[(d + 0) * 66 + sk];
            float2 k1 = *(const float2*)&kst[(d + 1) * 66 + sk];
            float2 k2 = *(const float2*)&kst[(d + 2) * 66 + sk];
            float2 k3 = *(const float2*)&kst[(d + 3) * 66 + sk];
            s00 += q0.x * k0.x + q0.y * k1.x + q0.z * k2.x + q0.w * k3.x;
            s01 += q0.x * k0.y + q0.y * k1.y + q0.z * k2.y + q0.w * k3.y;
            s10 += q1.x * k0.x + q1.y * k1.x + q1.z * k2.x + q1.w * k3.x;
            s11 += q1.x * k0.y + q1.y * k1.y + q1.z * k2.y + q1.w * k3.y;
        }
        int tokA = b * BS + dk;
        bool mA = (tokA <= t), mB = (tokA + 1 <= t);
        s00 = mA ? s00 * SCALE : NEGV;  s01 = mB ? s01 * SCALE : NEGV;
        s10 = mA ? s10 * SCALE : NEGV;  s11 = mB ? s11 * SCALE : NEGV;

        float c0 = fmaxf(s00, s01), c1 = fmaxf(s10, s11);
#pragma unroll
        for (int o = 16; o; o >>= 1) {
            c0 = fmaxf(c0, __shfl_xor_sync(0xffffffffu, c0, o));
            c1 = fmaxf(c1, __shfl_xor_sync(0xffffffffu, c1, o));
        }
        float mn0 = fmaxf(m0, c0), mn1 = fmaxf(m1, c1);
        float al0 = __expf(m0 - mn0), al1 = __expf(m1 - mn1);
        float p00 = __expf(s00 - mn0), p01 = __expf(s01 - mn0);
        float p10 = __expf(s10 - mn1), p11 = __expf(s11 - mn1);
        float ls0 = p00 + p01, ls1 = p10 + p11;
#pragma unroll
        for (int o = 16; o; o >>= 1) {
            ls0 += __shfl_xor_sync(0xffffffffu, ls0, o);
            ls1 += __shfl_xor_sync(0xffffffffu, ls1, o);
        }
        l0 = l0 * al0 + ls0;  l1 = l1 * al1 + ls1;
        m0 = mn0;  m1 = mn1;

        *(float2*)&psm[h0 * HD + dk] = make_float2(p00, p01);
        *(float2*)&psm[h1 * HD + dk] = make_float2(p10, p11);
        __syncwarp();

        // ---- PV: s in quads, float4 p-broadcasts ----
        acc0.x *= al0; acc0.y *= al0; acc1.x *= al1; acc1.y *= al1;
#pragma unroll
        for (int s = 0; s < BS; s += 4) {
            float4 p0 = *(const float4*)&psm[h0 * HD + s];
            float4 p1 = *(const float4*)&psm[h1 * HD + s];
            float2 v0 = *(const float2*)&vsm[(s + 0) * HD + dk];
            float2 v1 = *(const float2*)&vsm[(s + 1) * HD + dk];
            float2 v2 = *(const float2*)&vsm[(s + 2) * HD + dk];
            float2 v3 = *(const float2*)&vsm[(s + 3) * HD + dk];
            acc0.x += p0.x * v0.x + p0.y * v1.x + p0.z * v2.x + p0.w * v3.x;
            acc0.y += p0.x * v0.y + p0.y * v1.y + p0.z * v2.y + p0.w * v3.y;
            acc1.x += p1.x * v0.x + p1.y * v1.x + p1.z * v2.x + p1.w * v3.x;
            acc1.y += p1.x * v0.y + p1.y * v1.y + p1.z * v2.y + p1.w * v3.y;
        }
    }

    const float* pg = g_g + (size_t)t * 48;
    float gc0 = 1.f / (1.f + __expf(-pg[h0 * 3 + 0]));
    float gs0 = 1.f / (1.f + __expf(-pg[h0 * 3 + 1]));
    float gc1 = 1.f / (1.f + __expf(-pg[h1 * 3 + 0]));
    float gs1 = 1.f / (1.f + __expf(-pg[h1 * 3 + 1]));
    float inv0 = 1.f / l0, inv1 = 1.f / l1;
    float* od = g_o + (size_t)t * HQ * HD;
    od[h0 * HD + dk]     = acc0.x * inv0 * gs0 + ocmp[h0 * HD + dk]     * gc0;
    od[h0 * HD + dk + 1] = acc0.y * inv0 * gs0 + ocmp[h0 * HD + dk + 1] * gc0;
    od[h1 * HD + dk]     = acc1.x * inv1 * gs1 + ocmp[h1 * HD + dk]     * gc1;
    od[h1 * HD + dk + 1] = acc1.y * inv1 * gs1 + ocmp[h1 * HD + dk + 1] * gc1;
}

// ---------------- launch ----------------
extern "C" void kernel_launch(void* const* d_in, const int* in_sizes, int n_in,
                              void* d_out, int out_size)
{
    (void)in_sizes; (void)n_in; (void)out_size;
    const float* x  = (const float*)d_in[0];
    const float* Wq = (const float*)d_in[1];
    const float* Wk = (const float*)d_in[2];
    const float* Wv = (const float*)d_in[3];
    const float* Wg = (const float*)d_in[4];
    const float* Wo = (const float*)d_in[5];
    float* out = (float*)d_out;

    float *q, *o;
    cudaGetSymbolAddress((void**)&q, g_q);
    cudaGetSymbolAddress((void**)&o, g_o);

    dim3 blk(256);
    dim3 grid_big((DMODEL + 127) / 128, T_TOK / 128);

    sgemm_abt<<<grid_big, blk>>>(x, Wq, q, T_TOK, HQ * HD, DMODEL);
    proj_small<<<dim3(3, T_TOK / 64), blk>>>(x, Wk, Wv, Wg);
    pool_kv<<<NB, HD>>>();
    nsa_attn<<<T_TOK, 256>>>();
    sgemm_abt<<<grid_big, blk>>>(o, Wo, out, T_TOK, DMODEL, DMODEL);
}

// round 5
// speedup vs baseline: 1.8533x; 1.2557x over previous
#include <cuda_runtime.h>
#include <math.h>

#define T_TOK   2048
#define DMODEL  1024
#define HQ      16
#define HD      64
#define BS      64
#define SSEL    16
#define NB      32
#define NEGV    (-1e30f)
#define SCALE   0.125f

#define KS 68   // Ksm row stride (floats) - conflict-free B-frag LDS
#define VS 72   // Vsm row stride
#define PS 66   // psm row stride

// ---------------- device scratch ----------------
__device__ float g_q[T_TOK * HQ * HD];
__device__ float g_k[T_TOK * HD];
__device__ float g_v[T_TOK * HD];
__device__ float g_g[T_TOK * 48];
__device__ float g_kc[NB * HD];
__device__ float g_vc[NB * HD];
__device__ float g_o[T_TOK * HQ * HD];

// ---------------- mma helpers ----------------
__device__ __forceinline__ unsigned f2tf(float f) {
    unsigned u;
    asm("cvt.rna.tf32.f32 %0, %1;" : "=r"(u) : "f"(f));
    return u;
}

__device__ __forceinline__ void mma_tf32(float d[4], const unsigned a[4],
                                         unsigned b0, unsigned b1, const float c[4]) {
    asm volatile(
        "mma.sync.aligned.m16n8k8.row.col.f32.tf32.tf32.f32 "
        "{%0,%1,%2,%3}, {%4,%5,%6,%7}, {%8,%9}, {%10,%11,%12,%13};\n"
        : "=f"(d[0]), "=f"(d[1]), "=f"(d[2]), "=f"(d[3])
        : "r"(a[0]), "r"(a[1]), "r"(a[2]), "r"(a[3]), "r"(b0), "r"(b1),
          "f"(c[0]), "f"(c[1]), "f"(c[2]), "f"(c[3]));
}

__device__ __forceinline__ void store_frag(float* dst, float o[8][4], int l) {
    int r0 = l >> 2, cc = 2 * (l & 3);
#pragma unroll
    for (int nt = 0; nt < 8; nt++) {
        dst[r0 * 64 + nt * 8 + cc]           = o[nt][0];
        dst[r0 * 64 + nt * 8 + cc + 1]       = o[nt][1];
        dst[(r0 + 8) * 64 + nt * 8 + cc]     = o[nt][2];
        dst[(r0 + 8) * 64 + nt * 8 + cc + 1] = o[nt][3];
    }
}

__device__ __forceinline__ void add_frag(const float* src, float o[8][4], int l) {
    int r0 = l >> 2, cc = 2 * (l & 3);
#pragma unroll
    for (int nt = 0; nt < 8; nt++) {
        o[nt][0] += src[r0 * 64 + nt * 8 + cc];
        o[nt][1] += src[r0 * 64 + nt * 8 + cc + 1];
        o[nt][2] += src[(r0 + 8) * 64 + nt * 8 + cc];
        o[nt][3] += src[(r0 + 8) * 64 + nt * 8 + cc + 1];
    }
}

// ---------------- big SGEMM: C[M,N] = A[M,K] * B[N,K]^T ----------------
__global__ void __launch_bounds__(256, 2) sgemm_abt(
    const float* __restrict__ A, const float* __restrict__ B,
    float* __restrict__ C, int M, int N, int K)
{
    __shared__ float As[2][8][128];
    __shared__ float Bs[2][8][128];
    const int tid = threadIdx.x;
    const int tx = tid & 15, ty = tid >> 4;
    const int row0 = blockIdx.y * 128;
    const int col0 = blockIdx.x * 128;
    const int lr = tid >> 1;
    const int lc = (tid & 1) << 2;

    float acc[8][8] = {};
    const float* Ap = A + (size_t)(row0 + lr) * K + lc;
    const float* Bp = B + (size_t)(col0 + lr) * K + lc;
    const bool bok = (col0 + lr) < N;
    const int ntiles = K >> 3;

    {
        float4 a4 = *(const float4*)(Ap);
        float4 b4 = bok ? *(const float4*)(Bp) : make_float4(0.f, 0.f, 0.f, 0.f);
        As[0][lc + 0][lr] = a4.x; As[0][lc + 1][lr] = a4.y;
        As[0][lc + 2][lr] = a4.z; As[0][lc + 3][lr] = a4.w;
        Bs[0][lc + 0][lr] = b4.x; Bs[0][lc + 1][lr] = b4.y;
        Bs[0][lc + 2][lr] = b4.z; Bs[0][lc + 3][lr] = b4.w;
    }
    __syncthreads();

    int buf = 0;
    for (int tI = 0; tI < ntiles; tI++) {
        float4 na, nb_;
        const bool more = (tI + 1) < ntiles;
        if (more) {
            int k0 = (tI + 1) << 3;
            na  = *(const float4*)(Ap + k0);
            nb_ = bok ? *(const float4*)(Bp + k0) : make_float4(0.f, 0.f, 0.f, 0.f);
        }
#pragma unroll
        for (int kk = 0; kk < 8; kk++) {
            float av[8], bv[8];
            *(float4*)&av[0] = *(const float4*)&As[buf][kk][ty * 8];
            *(float4*)&av[4] = *(const float4*)&As[buf][kk][ty * 8 + 4];
            *(float4*)&bv[0] = *(const float4*)&Bs[buf][kk][tx * 8];
            *(float4*)&bv[4] = *(const float4*)&Bs[buf][kk][tx * 8 + 4];
#pragma unroll
            for (int i = 0; i < 8; i++)
#pragma unroll
                for (int j = 0; j < 8; j++)
                    acc[i][j] += av[i] * bv[j];
        }
        if (more) {
            int nbuf = buf ^ 1;
            As[nbuf][lc + 0][lr] = na.x;  As[nbuf][lc + 1][lr] = na.y;
            As[nbuf][lc + 2][lr] = na.z;  As[nbuf][lc + 3][lr] = na.w;
            Bs[nbuf][lc + 0][lr] = nb_.x; Bs[nbuf][lc + 1][lr] = nb_.y;
            Bs[nbuf][lc + 2][lr] = nb_.z; Bs[nbuf][lc + 3][lr] = nb_.w;
            __syncthreads();
            buf = nbuf;
        }
    }
#pragma unroll
    for (int i = 0; i < 8; i++) {
        int r = row0 + ty * 8 + i;
#pragma unroll
        for (int j = 0; j < 8; j++) {
            int c = col0 + tx * 8 + j;
            if (c < N) C[(size_t)r * N + c] = acc[i][j];
        }
    }
}

// ---------------- fused skinny projections: K, V, G ----------------
__global__ void __launch_bounds__(256, 2) proj_small(
    const float* __restrict__ x,
    const float* __restrict__ Wk, const float* __restrict__ Wv, const float* __restrict__ Wg)
{
    const int mat  = blockIdx.x;
    const int row0 = blockIdx.y * 64;
    const float* Bw = (mat == 0) ? Wk : (mat == 1) ? Wv : Wg;
    float* C        = (mat == 0) ? g_k : (mat == 1) ? g_v : g_g;
    const int N     = (mat == 2) ? 48 : 64;

    __shared__ float As[2][16][64];
    __shared__ float Bs[2][16][64];
    const int tid = threadIdx.x;
    const int tx = tid & 15, ty = tid >> 4;
    const int lr = tid >> 2;
    const int lk = (tid & 3) << 2;

    const float* Ap = x  + (size_t)(row0 + lr) * DMODEL + lk;
    const float* Bp = Bw + (size_t)lr * DMODEL + lk;
    const bool bok = lr < N;

    float acc[4][4] = {};
    {
        float4 a4 = *(const float4*)(Ap);
        float4 b4 = bok ? *(const float4*)(Bp) : make_float4(0.f, 0.f, 0.f, 0.f);
        As[0][lk + 0][lr] = a4.x; As[0][lk + 1][lr] = a4.y;
        As[0][lk + 2][lr] = a4.z; As[0][lk + 3][lr] = a4.w;
        Bs[0][lk + 0][lr] = b4.x; Bs[0][lk + 1][lr] = b4.y;
        Bs[0][lk + 2][lr] = b4.z; Bs[0][lk + 3][lr] = b4.w;
    }
    __syncthreads();

    const int ntiles = DMODEL / 16;
    int buf = 0;
    for (int tI = 0; tI < ntiles; tI++) {
        float4 na, nb_;
        const bool more = (tI + 1) < ntiles;
        if (more) {
            int k0 = (tI + 1) * 16;
            na  = *(const float4*)(Ap + k0);
            nb_ = bok ? *(const float4*)(Bp + k0) : make_float4(0.f, 0.f, 0.f, 0.f);
        }
#pragma unroll
        for (int kk = 0; kk < 16; kk++) {
            float av[4], bv[4];
            *(float4*)&av[0] = *(const float4*)&As[buf][kk][ty * 4];
            *(float4*)&bv[0] = *(const float4*)&Bs[buf][kk][tx * 4];
#pragma unroll
            for (int i = 0; i < 4; i++)
#pragma unroll
                for (int j = 0; j < 4; j++)
                    acc[i][j] += av[i] * bv[j];
        }
        if (more) {
            int nbuf = buf ^ 1;
            As[nbuf][lk + 0][lr] = na.x;  As[nbuf][lk + 1][lr] = na.y;
            As[nbuf][lk + 2][lr] = na.z;  As[nbuf][lk + 3][lr] = na.w;
            Bs[nbuf][lk + 0][lr] = nb_.x; Bs[nbuf][lk + 1][lr] = nb_.y;
            Bs[nbuf][lk + 2][lr] = nb_.z; Bs[nbuf][lk + 3][lr] = nb_.w;
            __syncthreads();
            buf = nbuf;
        }
    }
#pragma unroll
    for (int i = 0; i < 4; i++) {
        int r = row0 + ty * 4 + i;
#pragma unroll
        for (int j = 0; j < 4; j++) {
            int c = tx * 4 + j;
            if (c < N) C[(size_t)r * N + c] = acc[i][j];
        }
    }
}

// ---------------- mean-pool K/V ----------------
__global__ void pool_kv()
{
    int c = blockIdx.x;
    int d = threadIdx.x;
    float sk = 0.f, sv = 0.f;
    for (int s = 0; s < BS; s++) {
        sk += g_k[(c * BS + s) * HD + d];
        sv += g_v[(c * BS + s) * HD + d];
    }
    g_kc[c * HD + d] = sk * (1.f / BS);
    g_vc[c * HD + d] = sv * (1.f / BS);
}

// ---------------- fused per-token NSA (tensor-core selected attention) ----------------
__global__ void __launch_bounds__(256, 2) nsa_attn()
{
    const int t    = blockIdx.x;
    const int tid  = threadIdx.x;
    const int l    = tid & 31;
    const int wid  = tid >> 5;

    __shared__ __align__(16) float smem_big[64 * KS + 64 * VS];   // 8960 f
    __shared__ __align__(16) float qs[HQ * HD];
    __shared__ __align__(16) float psm[16 * PS];
    __shared__ float wmax[8 * 16];
    __shared__ float wsum[8 * 16];
    __shared__ float lstat[16];
    __shared__ float impS[NB];
    __shared__ int   sel[SSEL];

    float* kc  = smem_big;            // [32][65]
    float* vc  = smem_big + 2080;     // [32][66]
    float* Ksm = smem_big;            // [64][KS]
    float* Vsm = smem_big + 64 * KS;  // [64][VS]
    float* pbuf = psm;                // [16][32]

    const int cur  = t >> 6;
    const int nvis = (t + 1) >> 6;
    const float NINF = __int_as_float(0xff800000);

    // ---- load q row ----
    {
        const float4* qsrc = (const float4*)(g_q + (size_t)t * HQ * HD);
        ((float4*)qs)[tid] = qsrc[tid];
    }
    // ---- load compressed K/V ----
    for (int i = tid; i < NB * HD; i += 256) {
        int c = i >> 6, d = i & 63;
        kc[c * 65 + d] = g_kc[i];
        vc[c * 66 + d] = g_vc[i];
    }
    __syncthreads();

    // ---- compressed scores (fp32, exact -> selection stays exact) ----
    for (int i = tid; i < HQ * NB; i += 256) {
        int h = i >> 5, c = i & 31;
        const float* qh  = qs + h * HD;
        const float* kcc = kc + c * 65;
        float s = 0.f;
#pragma unroll
        for (int d = 0; d < HD; d++) s += qh[d] * kcc[d];
        pbuf[i] = (c < nvis) ? s * SCALE : NEGV;
    }
    __syncthreads();

    // ---- softmax over visible blocks ----
    for (int hh = 0; hh < 2; hh++) {
        int h = wid * 2 + hh;
        float v = pbuf[h * NB + l];
        float mx = v;
#pragma unroll
        for (int o = 16; o; o >>= 1) mx = fmaxf(mx, __shfl_xor_sync(0xffffffffu, mx, o));
        float e = (l < nvis) ? __expf(v - mx) : 0.f;
        float sm = e;
#pragma unroll
        for (int o = 16; o; o >>= 1) sm += __shfl_xor_sync(0xffffffffu, sm, o);
        pbuf[h * NB + l] = (sm > 0.f) ? e / sm : 0.f;
    }
    __syncthreads();

    // ---- o_cmp into registers (final write mapping: h0=2*wid, dims dk,dk+1) ----
    const int h0 = wid * 2, h1 = h0 + 1;
    const int dk = l * 2;
    float oc00 = 0.f, oc01 = 0.f, oc10 = 0.f, oc11 = 0.f;
#pragma unroll
    for (int c = 0; c < NB; c++) {
        float p0 = pbuf[h0 * NB + c];
        float p1 = pbuf[h1 * NB + c];
        float2 vv = *(const float2*)&vc[c * 66 + dk];
        oc00 += p0 * vv.x; oc01 += p0 * vv.y;
        oc10 += p1 * vv.x; oc11 += p1 * vv.y;
    }

    // ---- importance + top-16 ----
    if (tid < NB) {
        int c = tid;
        float s = 0.f;
#pragma unroll
        for (int h = 0; h < HQ; h++) s += pbuf[h * NB + c];
        if (c > cur) s = NEGV;
        if (c == 0 || c == cur) s = __int_as_float(0x7f800000);
        impS[c] = s;
    }
    __syncthreads();
    if (tid == 0) {
        for (int it = 0; it < SSEL; it++) {
            float best = NINF; int bi = 0;
            for (int c = 0; c < NB; c++) {
                float v = impS[c];
                if (v > best) { best = v; bi = c; }
            }
            sel[it] = bi;
            impS[bi] = NINF;
        }
    }
    __syncthreads();   // FIX: publish sel[] before any warp reads it (R4 crash: race -> garbage block idx -> OOB)

    // ---- preload Q A-fragments (tf32), m16 x k8 tiles ----
    const int r0 = l >> 2;             // head row 0..7 (and +8)
    const int tg = l & 3;              // thread-in-group
    unsigned aQ[8][4];
#pragma unroll
    for (int kt = 0; kt < 8; kt++) {
        aQ[kt][0] = f2tf(qs[r0 * HD + kt * 8 + tg]);
        aQ[kt][1] = f2tf(qs[(r0 + 8) * HD + kt * 8 + tg]);
        aQ[kt][2] = f2tf(qs[r0 * HD + kt * 8 + tg + 4]);
        aQ[kt][3] = f2tf(qs[(r0 + 8) * HD + kt * 8 + tg + 4]);
    }

    // ---- selected attention: 16 chunks of 64 keys, warp w owns keys [8w,8w+8) ----
    float o[8][4] = {};
    float m0 = NEGV, m1 = NEGV, l0 = 0.f, l1 = 0.f;

    for (int ib = 0; ib < SSEL; ib++) {
        int b = sel[ib];
        __syncthreads();   // previous chunk's smem reads done (also fences phase A)
        const float4* kg = (const float4*)(g_k + (size_t)b * BS * HD);
        const float4* vg = (const float4*)(g_v + (size_t)b * BS * HD);
#pragma unroll
        for (int r = 0; r < 4; r++) {
            int f = tid + r * 256;
            int key = f >> 4, dq = (f & 15) << 2;
            *(float4*)&Ksm[key * KS + dq] = kg[f];
            *(float4*)&Vsm[key * VS + dq] = vg[f];
        }
        __syncthreads();

        // S = Q . K^T for this warp's 8-key slice
        float c[4] = {0.f, 0.f, 0.f, 0.f};
#pragma unroll
        for (int kt = 0; kt < 8; kt++) {
            const float* kr = &Ksm[(8 * wid + r0) * KS + kt * 8 + tg];
            unsigned b0 = f2tf(kr[0]);
            unsigned b1 = f2tf(kr[4]);
            mma_tf32(c, aQ[kt], b0, b1, c);
        }
        int kb = b * BS + 8 * wid + 2 * tg;
        bool mA = (kb <= t), mB = (kb + 1 <= t);
        c[0] = mA ? c[0] * SCALE : NEGV;
        c[1] = mB ? c[1] * SCALE : NEGV;
        c[2] = mA ? c[2] * SCALE : NEGV;
        c[3] = mB ? c[3] * SCALE : NEGV;

        float x0 = fmaxf(c[0], c[1]), x1 = fmaxf(c[2], c[3]);
        x0 = fmaxf(x0, __shfl_xor_sync(0xffffffffu, x0, 1));
        x0 = fmaxf(x0, __shfl_xor_sync(0xffffffffu, x0, 2));
        x1 = fmaxf(x1, __shfl_xor_sync(0xffffffffu, x1, 1));
        x1 = fmaxf(x1, __shfl_xor_sync(0xffffffffu, x1, 2));
        if (tg == 0) { wmax[wid * 16 + r0] = x0; wmax[wid * 16 + 8 + r0] = x1; }
        __syncthreads();

        float gm0 = NINF, gm1 = NINF;
#pragma unroll
        for (int w = 0; w < 8; w++) {
            gm0 = fmaxf(gm0, wmax[w * 16 + r0]);
            gm1 = fmaxf(gm1, wmax[w * 16 + 8 + r0]);
        }
        float mn0 = fmaxf(m0, gm0), mn1 = fmaxf(m1, gm1);
        float al0 = __expf(m0 - mn0), al1 = __expf(m1 - mn1);
        float p0 = __expf(c[0] - mn0), p1 = __expf(c[1] - mn0);
        float p2 = __expf(c[2] - mn1), p3 = __expf(c[3] - mn1);
        float s0 = p0 + p1, s1 = p2 + p3;
        s0 += __shfl_xor_sync(0xffffffffu, s0, 1);
        s0 += __shfl_xor_sync(0xffffffffu, s0, 2);
        s1 += __shfl_xor_sync(0xffffffffu, s1, 1);
        s1 += __shfl_xor_sync(0xffffffffu, s1, 2);
        if (tg == 0) { wsum[wid * 16 + r0] = s0; wsum[wid * 16 + 8 + r0] = s1; }

        psm[r0 * PS + 8 * wid + 2 * tg]           = p0;
        psm[r0 * PS + 8 * wid + 2 * tg + 1]       = p1;
        psm[(r0 + 8) * PS + 8 * wid + 2 * tg]     = p2;
        psm[(r0 + 8) * PS + 8 * wid + 2 * tg + 1] = p3;
        __syncthreads();

        float gs0 = 0.f, gs1 = 0.f;
#pragma unroll
        for (int w = 0; w < 8; w++) {
            gs0 += wsum[w * 16 + r0];
            gs1 += wsum[w * 16 + 8 + r0];
        }
        l0 = l0 * al0 + gs0;  l1 = l1 * al1 + gs1;
        m0 = mn0;  m1 = mn1;

        unsigned ap[4];
        ap[0] = f2tf(psm[r0 * PS + 8 * wid + tg]);
        ap[1] = f2tf(psm[(r0 + 8) * PS + 8 * wid + tg]);
        ap[2] = f2tf(psm[r0 * PS + 8 * wid + tg + 4]);
        ap[3] = f2tf(psm[(r0 + 8) * PS + 8 * wid + tg + 4]);

#pragma unroll
        for (int nt = 0; nt < 8; nt++) {
            o[nt][0] *= al0; o[nt][1] *= al0;
            o[nt][2] *= al1; o[nt][3] *= al1;
            unsigned b0 = f2tf(Vsm[(8 * wid + tg) * VS + nt * 8 + r0]);
            unsigned b1 = f2tf(Vsm[(8 * wid + tg + 4) * VS + nt * 8 + r0]);
            mma_tf32(o[nt], ap, b0, b1, o[nt]);
        }
    }

    // ---- cross-warp O reduction (tree, scratch aliases Ksm region) ----
    __syncthreads();
    if (wid >= 4) store_frag(smem_big + (wid - 4) * 1024, o, l);
    __syncthreads();
    if (wid < 4) add_frag(smem_big + wid * 1024, o, l);
    __syncthreads();
    if (wid == 2 || wid == 3) store_frag(smem_big + (wid - 2) * 1024, o, l);
    __syncthreads();
    if (wid < 2) add_frag(smem_big + wid * 1024, o, l);
    __syncthreads();
    if (wid == 1) store_frag(smem_big, o, l);
    __syncthreads();
    if (wid == 0) {
        add_frag(smem_big, o, l);
        store_frag(smem_big, o, l);
        if (tg == 0) { lstat[r0] = l0; lstat[8 + r0] = l1; }
    }
    __syncthreads();

    // ---- gate + combine + write ----
    const float* pg = g_g + (size_t)t * 48;
    float gc0 = 1.f / (1.f + __expf(-pg[h0 * 3 + 0]));
    float gs_0 = 1.f / (1.f + __expf(-pg[h0 * 3 + 1]));
    float gc1 = 1.f / (1.f + __expf(-pg[h1 * 3 + 0]));
    float gs_1 = 1.f / (1.f + __expf(-pg[h1 * 3 + 1]));
    float li0 = 1.f / lstat[h0], li1 = 1.f / lstat[h1];
    float2 os0 = *(const float2*)&smem_big[h0 * 64 + dk];
    float2 os1 = *(const float2*)&smem_big[h1 * 64 + dk];
    float* od = g_o + (size_t)t * HQ * HD;
    od[h0 * HD + dk]     = os0.x * li0 * gs_0 + oc00 * gc0;
    od[h0 * HD + dk + 1] = os0.y * li0 * gs_0 + oc01 * gc0;
    od[h1 * HD + dk]     = os1.x * li1 * gs_1 + oc10 * gc1;
    od[h1 * HD + dk + 1] = os1.y * li1 * gs_1 + oc11 * gc1;
}

// ---------------- launch ----------------
extern "C" void kernel_launch(void* const* d_in, const int* in_sizes, int n_in,
                              void* d_out, int out_size)
{
    (void)in_sizes; (void)n_in; (void)out_size;
    const float* x  = (const float*)d_in[0];
    const float* Wq = (const float*)d_in[1];
    const float* Wk = (const float*)d_in[2];
    const float* Wv = (const float*)d_in[3];
    const float* Wg = (const float*)d_in[4];
    const float* Wo = (const float*)d_in[5];
    float* out = (float*)d_out;

    float *q, *o;
    cudaGetSymbolAddress((void**)&q, g_q);
    cudaGetSymbolAddress((void**)&o, g_o);

    dim3 blk(256);
    dim3 grid_big((DMODEL + 127) / 128, T_TOK / 128);

    sgemm_abt<<<grid_big, blk>>>(x, Wq, q, T_TOK, HQ * HD, DMODEL);
    proj_small<<<dim3(3, T_TOK / 64), blk>>>(x, Wk, Wv, Wg);
    pool_kv<<<NB, HD>>>();
    nsa_attn<<<T_TOK, 256>>>();
    sgemm_abt<<<grid_big, blk>>>(o, Wo, out, T_TOK, DMODEL, DMODEL);
}